// round 6
// baseline (speedup 1.0000x reference)
#include <cuda_runtime.h>
#include <math.h>

// ---------------- scratch ----------------
__device__ float g_h1[16777216];      // 32768*512 (reused; also 4096*2048)
__device__ float g_df[16777216];      // 32768*512
__device__ float g_ef[33652736];      // 32768*1027
__device__ float g_coords[65536];     // 32768*2
__device__ float g_imp[32768];
__device__ int   g_top[4096];         // 8*512
__device__ float g_pos[8192];         // 8*512*2
__device__ float g_states[4194304];   // 4096*1024
__device__ float g_proj[2097152];     // 4096*512
__device__ float g_We2p[589824];      // 512*1152 padded We2

__device__ __forceinline__ float gelu_f(float x) {
    return 0.5f * x * (1.0f + erff(x * 0.70710678118654752440f));
}

// ---- packed fp32x2 helpers (bit-exact fp32, 2x FMA throughput) ----
__device__ __forceinline__ unsigned long long pack2(float x) {
    unsigned long long r;
    asm("mov.b64 %0, {%1, %1};" : "=l"(r) : "f"(x));
    return r;
}
__device__ __forceinline__ void fma2(unsigned long long& d,
                                     unsigned long long a,
                                     unsigned long long b) {
    asm("fma.rn.f32x2 %0, %1, %2, %0;" : "+l"(d) : "l"(a), "l"(b));
}
__device__ __forceinline__ float2 unpack2(unsigned long long p) {
    float2 f;
    asm("mov.b64 {%0, %1}, %2;" : "=f"(f.x), "=f"(f.y) : "l"(p));
    return f;
}

// ---------------- pad We2 (512,1027) -> (512,1152) zero-filled ----------------
__global__ void __launch_bounds__(256) padB_k(const float* __restrict__ src,
                                              float* __restrict__ dst)
{
    int i = blockIdx.x * 256 + threadIdx.x;
    if (i >= 512 * 1152) return;
    int r = i / 1152, c = i - r * 1152;
    dst[i] = (c < 1027) ? src[r * 1027 + c] : 0.0f;
}

// ---------------- tiled fp32 GEMM, 128x128x16, 8x8 per thread, FFMA2 core ----------------
template<int EPI, bool NG>
__global__ void __launch_bounds__(256, 2) gemm_k(
    const float* __restrict__ A, const float* __restrict__ B,
    const float* __restrict__ bias, float* __restrict__ C,
    int M, int N, int K, int ldb,
    const float* __restrict__ coords, const float* __restrict__ wtop)
{
    __shared__ __align__(16) unsigned long long As2[16][130];
    __shared__ __align__(16) float Bs[16][128];

    const int tid = threadIdx.x;
    const int bm  = blockIdx.y * 128;
    const int bn  = blockIdx.x * 128;
    const int tx  = tid & 15;
    const int ty  = tid >> 4;
    const int row = ty * 8;

    unsigned long long acc2[8][4];
    #pragma unroll
    for (int i = 0; i < 8; i++)
        #pragma unroll
        for (int p = 0; p < 4; p++) acc2[i][p] = 0ULL;

    const int rA0 = tid >> 2;
    const int cA4 = tid & 3;
    const int rB0 = tid >> 5;
    const int cB  = (tid & 31) * 4;

    float4 ra0, ra1, rb0, rb1;

    ra0 = *reinterpret_cast<const float4*>(A + (size_t)(bm + rA0) * K + cA4 * 4);
    ra1 = *reinterpret_cast<const float4*>(A + (size_t)(bm + rA0 + 64) * K + cA4 * 4);
    rb0 = *reinterpret_cast<const float4*>(B + (size_t)rB0 * ldb + bn + cB);
    rb1 = *reinterpret_cast<const float4*>(B + (size_t)(rB0 + 8) * ldb + bn + cB);

    for (int k0 = 0; k0 < K; k0 += 16) {
        __syncthreads();
        As2[cA4 * 4 + 0][rA0] = pack2(ra0.x);
        As2[cA4 * 4 + 1][rA0] = pack2(ra0.y);
        As2[cA4 * 4 + 2][rA0] = pack2(ra0.z);
        As2[cA4 * 4 + 3][rA0] = pack2(ra0.w);
        As2[cA4 * 4 + 0][rA0 + 64] = pack2(ra1.x);
        As2[cA4 * 4 + 1][rA0 + 64] = pack2(ra1.y);
        As2[cA4 * 4 + 2][rA0 + 64] = pack2(ra1.z);
        As2[cA4 * 4 + 3][rA0 + 64] = pack2(ra1.w);
        *reinterpret_cast<float4*>(&Bs[rB0][cB])     = rb0;
        *reinterpret_cast<float4*>(&Bs[rB0 + 8][cB]) = rb1;
        __syncthreads();

        if (k0 + 16 < K) {
            int kn = k0 + 16;
            ra0 = *reinterpret_cast<const float4*>(A + (size_t)(bm + rA0) * K + kn + cA4 * 4);
            ra1 = *reinterpret_cast<const float4*>(A + (size_t)(bm + rA0 + 64) * K + kn + cA4 * 4);
            rb0 = *reinterpret_cast<const float4*>(B + (size_t)(kn + rB0) * ldb + bn + cB);
            rb1 = *reinterpret_cast<const float4*>(B + (size_t)(kn + rB0 + 8) * ldb + bn + cB);
        }

        #pragma unroll
        for (int k = 0; k < 16; k++) {
            ulonglong2 A0 = *reinterpret_cast<const ulonglong2*>(&As2[k][row]);
            ulonglong2 A1 = *reinterpret_cast<const ulonglong2*>(&As2[k][row + 2]);
            ulonglong2 A2 = *reinterpret_cast<const ulonglong2*>(&As2[k][row + 4]);
            ulonglong2 A3 = *reinterpret_cast<const ulonglong2*>(&As2[k][row + 6]);
            ulonglong2 B0 = *reinterpret_cast<const ulonglong2*>(&Bs[k][tx * 4]);
            ulonglong2 B1 = *reinterpret_cast<const ulonglong2*>(&Bs[k][64 + tx * 4]);
            fma2(acc2[0][0], A0.x, B0.x); fma2(acc2[0][1], A0.x, B0.y);
            fma2(acc2[0][2], A0.x, B1.x); fma2(acc2[0][3], A0.x, B1.y);
            fma2(acc2[1][0], A0.y, B0.x); fma2(acc2[1][1], A0.y, B0.y);
            fma2(acc2[1][2], A0.y, B1.x); fma2(acc2[1][3], A0.y, B1.y);
            fma2(acc2[2][0], A1.x, B0.x); fma2(acc2[2][1], A1.x, B0.y);
            fma2(acc2[2][2], A1.x, B1.x); fma2(acc2[2][3], A1.x, B1.y);
            fma2(acc2[3][0], A1.y, B0.x); fma2(acc2[3][1], A1.y, B0.y);
            fma2(acc2[3][2], A1.y, B1.x); fma2(acc2[3][3], A1.y, B1.y);
            fma2(acc2[4][0], A2.x, B0.x); fma2(acc2[4][1], A2.x, B0.y);
            fma2(acc2[4][2], A2.x, B1.x); fma2(acc2[4][3], A2.x, B1.y);
            fma2(acc2[5][0], A2.y, B0.x); fma2(acc2[5][1], A2.y, B0.y);
            fma2(acc2[5][2], A2.y, B1.x); fma2(acc2[5][3], A2.y, B1.y);
            fma2(acc2[6][0], A3.x, B0.x); fma2(acc2[6][1], A3.x, B0.y);
            fma2(acc2[6][2], A3.x, B1.x); fma2(acc2[6][3], A3.x, B1.y);
            fma2(acc2[7][0], A3.y, B0.x); fma2(acc2[7][1], A3.y, B0.y);
            fma2(acc2[7][2], A3.y, B1.x); fma2(acc2[7][3], A3.y, B1.y);
        }
    }

    float acc[8][8];
    #pragma unroll
    for (int i = 0; i < 8; i++)
        #pragma unroll
        for (int p = 0; p < 4; p++) {
            float2 t = unpack2(acc2[i][p]);
            acc[i][p * 2 + 0] = t.x;
            acc[i][p * 2 + 1] = t.y;
        }

    float bs[8], w0[8], w1[8];
    #pragma unroll
    for (int h = 0; h < 2; h++)
        #pragma unroll
        for (int jj = 0; jj < 4; jj++) {
            int j = h * 4 + jj;
            int n = bn + h * 64 + tx * 4 + jj;
            bool ok = !NG || (n < N);
            bs[j] = ok ? bias[n] : 0.0f;
            if (EPI == 2) { w0[j] = ok ? wtop[n] : 0.0f; w1[j] = ok ? wtop[512 + n] : 0.0f; }
        }

    #pragma unroll
    for (int i = 0; i < 8; i++) {
        int gm = bm + row + i;
        float c0 = 0.0f, c1 = 0.0f;
        if (EPI == 2) { c0 = coords[(size_t)gm * 2]; c1 = coords[(size_t)gm * 2 + 1]; }
        #pragma unroll
        for (int h = 0; h < 2; h++) {
            int nb = bn + h * 64 + tx * 4;
            if (!NG) {
                float t[4];
                #pragma unroll
                for (int jj = 0; jj < 4; jj++) {
                    int j = h * 4 + jj;
                    float val = acc[i][j] + bs[j];
                    if (EPI == 2) val += c0 * w0[j] + c1 * w1[j];
                    if (EPI >= 1) val = gelu_f(val);
                    t[jj] = val;
                }
                float4 v; v.x = t[0]; v.y = t[1]; v.z = t[2]; v.w = t[3];
                *reinterpret_cast<float4*>(C + (size_t)gm * N + nb) = v;
            } else {
                #pragma unroll
                for (int jj = 0; jj < 4; jj++) {
                    int j = h * 4 + jj;
                    int n = nb + jj;
                    if (n < N) {
                        float val = acc[i][j] + bs[j];
                        if (EPI >= 1) val = gelu_f(val);
                        C[(size_t)gm * N + n] = val;
                    }
                }
            }
        }
    }
}

// ---------------- 64x128-tile GEMM (EPI=0), 128 threads, 4 CTAs/SM ----------------
__global__ void __launch_bounds__(128, 4) gemm64_k(
    const float* __restrict__ A, const float* __restrict__ B,
    const float* __restrict__ bias, float* __restrict__ C,
    int M, int N, int K, int ldb)
{
    __shared__ __align__(16) unsigned long long As2[16][66];
    __shared__ __align__(16) float Bs[16][128];

    const int tid = threadIdx.x;
    const int bm  = blockIdx.y * 64;
    const int bn  = blockIdx.x * 128;
    const int tx  = tid & 15;
    const int ty  = tid >> 4;          // 0..7
    const int row = ty * 8;

    unsigned long long acc2[8][4];
    #pragma unroll
    for (int i = 0; i < 8; i++)
        #pragma unroll
        for (int p = 0; p < 4; p++) acc2[i][p] = 0ULL;

    const int rA0 = tid >> 2;          // 0..31 (and +32)
    const int cA4 = tid & 3;
    const int rB0 = tid >> 5;          // 0..3 (stride 4 over 16 rows)
    const int cB  = (tid & 31) * 4;

    float4 ra0, ra1;
    float4 rb[4];

    ra0 = *reinterpret_cast<const float4*>(A + (size_t)(bm + rA0) * K + cA4 * 4);
    ra1 = *reinterpret_cast<const float4*>(A + (size_t)(bm + rA0 + 32) * K + cA4 * 4);
    #pragma unroll
    for (int i = 0; i < 4; i++)
        rb[i] = *reinterpret_cast<const float4*>(B + (size_t)(rB0 + i * 4) * ldb + bn + cB);

    for (int k0 = 0; k0 < K; k0 += 16) {
        __syncthreads();
        As2[cA4 * 4 + 0][rA0] = pack2(ra0.x);
        As2[cA4 * 4 + 1][rA0] = pack2(ra0.y);
        As2[cA4 * 4 + 2][rA0] = pack2(ra0.z);
        As2[cA4 * 4 + 3][rA0] = pack2(ra0.w);
        As2[cA4 * 4 + 0][rA0 + 32] = pack2(ra1.x);
        As2[cA4 * 4 + 1][rA0 + 32] = pack2(ra1.y);
        As2[cA4 * 4 + 2][rA0 + 32] = pack2(ra1.z);
        As2[cA4 * 4 + 3][rA0 + 32] = pack2(ra1.w);
        #pragma unroll
        for (int i = 0; i < 4; i++)
            *reinterpret_cast<float4*>(&Bs[rB0 + i * 4][cB]) = rb[i];
        __syncthreads();

        if (k0 + 16 < K) {
            int kn = k0 + 16;
            ra0 = *reinterpret_cast<const float4*>(A + (size_t)(bm + rA0) * K + kn + cA4 * 4);
            ra1 = *reinterpret_cast<const float4*>(A + (size_t)(bm + rA0 + 32) * K + kn + cA4 * 4);
            #pragma unroll
            for (int i = 0; i < 4; i++)
                rb[i] = *reinterpret_cast<const float4*>(B + (size_t)(kn + rB0 + i * 4) * ldb + bn + cB);
        }

        #pragma unroll
        for (int k = 0; k < 16; k++) {
            ulonglong2 A0 = *reinterpret_cast<const ulonglong2*>(&As2[k][row]);
            ulonglong2 A1 = *reinterpret_cast<const ulonglong2*>(&As2[k][row + 2]);
            ulonglong2 A2 = *reinterpret_cast<const ulonglong2*>(&As2[k][row + 4]);
            ulonglong2 A3 = *reinterpret_cast<const ulonglong2*>(&As2[k][row + 6]);
            ulonglong2 B0 = *reinterpret_cast<const ulonglong2*>(&Bs[k][tx * 4]);
            ulonglong2 B1 = *reinterpret_cast<const ulonglong2*>(&Bs[k][64 + tx * 4]);
            fma2(acc2[0][0], A0.x, B0.x); fma2(acc2[0][1], A0.x, B0.y);
            fma2(acc2[0][2], A0.x, B1.x); fma2(acc2[0][3], A0.x, B1.y);
            fma2(acc2[1][0], A0.y, B0.x); fma2(acc2[1][1], A0.y, B0.y);
            fma2(acc2[1][2], A0.y, B1.x); fma2(acc2[1][3], A0.y, B1.y);
            fma2(acc2[2][0], A1.x, B0.x); fma2(acc2[2][1], A1.x, B0.y);
            fma2(acc2[2][2], A1.x, B1.x); fma2(acc2[2][3], A1.x, B1.y);
            fma2(acc2[3][0], A1.y, B0.x); fma2(acc2[3][1], A1.y, B0.y);
            fma2(acc2[3][2], A1.y, B1.x); fma2(acc2[3][3], A1.y, B1.y);
            fma2(acc2[4][0], A2.x, B0.x); fma2(acc2[4][1], A2.x, B0.y);
            fma2(acc2[4][2], A2.x, B1.x); fma2(acc2[4][3], A2.x, B1.y);
            fma2(acc2[5][0], A2.y, B0.x); fma2(acc2[5][1], A2.y, B0.y);
            fma2(acc2[5][2], A2.y, B1.x); fma2(acc2[5][3], A2.y, B1.y);
            fma2(acc2[6][0], A3.x, B0.x); fma2(acc2[6][1], A3.x, B0.y);
            fma2(acc2[6][2], A3.x, B1.x); fma2(acc2[6][3], A3.x, B1.y);
            fma2(acc2[7][0], A3.y, B0.x); fma2(acc2[7][1], A3.y, B0.y);
            fma2(acc2[7][2], A3.y, B1.x); fma2(acc2[7][3], A3.y, B1.y);
        }
    }

    float bs[8];
    #pragma unroll
    for (int h = 0; h < 2; h++)
        #pragma unroll
        for (int jj = 0; jj < 4; jj++)
            bs[h * 4 + jj] = bias[bn + h * 64 + tx * 4 + jj];

    #pragma unroll
    for (int i = 0; i < 8; i++) {
        int gm = bm + row + i;
        #pragma unroll
        for (int h = 0; h < 2; h++) {
            float2 t0 = unpack2(acc2[i][h * 2]);
            float2 t1 = unpack2(acc2[i][h * 2 + 1]);
            float4 v;
            v.x = t0.x + bs[h * 4 + 0];
            v.y = t0.y + bs[h * 4 + 1];
            v.z = t1.x + bs[h * 4 + 2];
            v.w = t1.y + bs[h * 4 + 3];
            *reinterpret_cast<float4*>(C + (size_t)gm * N + bn + h * 64 + tx * 4) = v;
        }
    }
}

// ---------------- coords: (32768,512) @ (512,2) + bc, float4 ----------------
__global__ void __launch_bounds__(256) coords_k(
    const float* __restrict__ df, const float* __restrict__ Wc,
    const float* __restrict__ bc, float* __restrict__ coords)
{
    int r    = blockIdx.x * 8 + (threadIdx.x >> 5);
    int lane = threadIdx.x & 31;
    if (r >= 32768) return;
    const float4* rowp = reinterpret_cast<const float4*>(df + (size_t)r * 512);
    const float4* wc4  = reinterpret_cast<const float4*>(Wc);
    float c0 = 0.0f, c1 = 0.0f;
    #pragma unroll
    for (int it = 0; it < 4; it++) {
        int k4 = it * 32 + lane;            // float4 index, covers k = k4*4..+3
        float4 d = rowp[k4];
        float4 a = wc4[k4 * 2];             // pairs for k, k+1
        float4 b = wc4[k4 * 2 + 1];         // pairs for k+2, k+3
        c0 = fmaf(d.x, a.x, c0); c1 = fmaf(d.x, a.y, c1);
        c0 = fmaf(d.y, a.z, c0); c1 = fmaf(d.y, a.w, c1);
        c0 = fmaf(d.z, b.x, c0); c1 = fmaf(d.z, b.y, c1);
        c0 = fmaf(d.w, b.z, c0); c1 = fmaf(d.w, b.w, c1);
    }
    #pragma unroll
    for (int o = 16; o; o >>= 1) {
        c0 += __shfl_xor_sync(0xffffffffu, c0, o);
        c1 += __shfl_xor_sync(0xffffffffu, c1, o);
    }
    if (lane == 0) {
        coords[(size_t)r * 2]     = c0 + bc[0];
        coords[(size_t)r * 2 + 1] = c1 + bc[1];
    }
}

// ---------------- importance: row L2 norm over 1027 ----------------
__global__ void __launch_bounds__(256) imp_k(
    const float* __restrict__ ef, float* __restrict__ imp)
{
    int r    = blockIdx.x * 8 + (threadIdx.x >> 5);
    int lane = threadIdx.x & 31;
    if (r >= 32768) return;
    const float* rowp = ef + (size_t)r * 1027;
    float s = 0.0f;
    for (int k = lane; k < 1027; k += 32) {
        float v = rowp[k];
        s = fmaf(v, v, s);
    }
    #pragma unroll
    for (int o = 16; o; o >>= 1) s += __shfl_xor_sync(0xffffffffu, s, o);
    if (lane == 0) imp[r] = sqrtf(s);
}

// ---------------- top-512 of 4096 per batch ----------------
__global__ void __launch_bounds__(1024) topk_k(
    const float* __restrict__ imp, int* __restrict__ top)
{
    __shared__ unsigned long long key[4096];
    int b   = blockIdx.x;
    int tid = threadIdx.x;
    for (int s = tid; s < 4096; s += 1024) {
        unsigned int bits = __float_as_uint(imp[b * 4096 + s]);
        key[s] = ((unsigned long long)(~bits) << 32) | (unsigned int)s;
    }
    for (int k = 2; k <= 4096; k <<= 1) {
        for (int j = k >> 1; j > 0; j >>= 1) {
            __syncthreads();
            for (int idx = tid; idx < 4096; idx += 1024) {
                int l = idx ^ j;
                if (l > idx) {
                    bool asc = ((idx & k) == 0);
                    unsigned long long a = key[idx], c = key[l];
                    if ((a > c) == asc) { key[idx] = c; key[l] = a; }
                }
            }
        }
    }
    __syncthreads();
    if (tid < 512) top[b * 512 + tid] = (int)(key[tid] & 0xffffffffu);
}

// ---------------- gather selected rows ----------------
__global__ void __launch_bounds__(256) gather_k(
    const float* __restrict__ ef, const int* __restrict__ top,
    float* __restrict__ pos, float* __restrict__ states)
{
    int rowi = blockIdx.x;
    int b    = rowi >> 9;
    int s    = top[rowi];
    const float* src = ef + (size_t)(b * 4096 + s) * 1027;
    if (threadIdx.x < 2) pos[rowi * 2 + threadIdx.x] = src[threadIdx.x];
    for (int d = threadIdx.x; d < 1024; d += 256)
        states[(size_t)rowi * 1024 + d] = src[2 + d];
}

// ---------------- fused gaussian attention + einsum ----------------
// 32 grid points x 512 entities per block; thread: 8 g-rows x 8 d-cols
__global__ void __launch_bounds__(256, 2) attn_k(
    const float* __restrict__ pos, const float* __restrict__ proj,
    float* __restrict__ out)
{
    extern __shared__ float sm[];
    float* spx  = sm;                  // 512
    float* spy  = spx + 512;           // 512
    float* sa   = spy + 512;           // 32*512
    float* rinv = sa + 32 * 512;       // 32

    const int b   = blockIdx.y;
    const int g0  = blockIdx.x * 32;
    const int tid = threadIdx.x;

    for (int n = tid; n < 512; n += 256) {
        spx[n] = pos[(b * 512 + n) * 2];
        spy[n] = pos[(b * 512 + n) * 2 + 1];
    }
    __syncthreads();

    for (int e = tid; e < 32 * 512; e += 256) {
        int i  = e >> 9;
        int n  = e & 511;
        int gi = g0 + i;
        float a = 0.0f;
        if (gi < 10000) {
            int ix = gi / 100, iy = gi - ix * 100;
            float gx = (ix == 99) ? 1.0f : -1.0f + (float)ix * (2.0f / 99.0f);
            float gy = (iy == 99) ? 1.0f : -1.0f + (float)iy * (2.0f / 99.0f);
            float dx = gx - spx[n];
            float dy = gy - spy[n];
            float sq = fmaf(dx, dx, dy * dy);
            a = __expf(sq * -10.0f);
        }
        sa[i * 512 + n] = a;
    }
    __syncthreads();

    int warp = tid >> 5, lane = tid & 31;
    for (int i = warp; i < 32; i += 8) {
        float s = 0.0f;
        for (int n = lane; n < 512; n += 32) s += sa[i * 512 + n];
        #pragma unroll
        for (int o = 16; o; o >>= 1) s += __shfl_xor_sync(0xffffffffu, s, o);
        if (lane == 0) rinv[i] = 1.0f / (s + 1e-8f);
    }
    __syncthreads();

    // 32x512 = sa(32x512) @ proj_b(512x512); thread: 8 rows x 8 cols
    const int gg = tid >> 6;           // 0..3 -> rows gg*8..+7
    const int dt = tid & 63;           // cols dt*8..+7
    const float* pb = proj + (size_t)b * 512 * 512 + dt * 8;
    unsigned long long acc[8][4];
    #pragma unroll
    for (int i = 0; i < 8; i++)
        #pragma unroll
        for (int p = 0; p < 4; p++) acc[i][p] = 0ULL;

    const float* sarow = sa + gg * 8 * 512;

    #pragma unroll 2
    for (int n = 0; n < 512; n++) {
        unsigned long long pa[8];
        #pragma unroll
        for (int i = 0; i < 8; i++) pa[i] = pack2(sarow[i * 512 + n]);
        ulonglong2 v0 = *reinterpret_cast<const ulonglong2*>(pb + (size_t)n * 512);
        ulonglong2 v1 = *reinterpret_cast<const ulonglong2*>(pb + (size_t)n * 512 + 4);
        #pragma unroll
        for (int i = 0; i < 8; i++) {
            fma2(acc[i][0], pa[i], v0.x);
            fma2(acc[i][1], pa[i], v0.y);
            fma2(acc[i][2], pa[i], v1.x);
            fma2(acc[i][3], pa[i], v1.y);
        }
    }

    #pragma unroll
    for (int i = 0; i < 8; i++) {
        int gi = g0 + gg * 8 + i;
        if (gi < 10000) {
            float r = rinv[gg * 8 + i];
            float* o = out + ((size_t)b * 10000 + gi) * 512 + dt * 8;
            float2 t0 = unpack2(acc[i][0]);
            float2 t1 = unpack2(acc[i][1]);
            float2 t2 = unpack2(acc[i][2]);
            float2 t3 = unpack2(acc[i][3]);
            float4 v;
            v.x = t0.x * r; v.y = t0.y * r; v.z = t1.x * r; v.w = t1.y * r;
            *reinterpret_cast<float4*>(o) = v;
            v.x = t2.x * r; v.y = t2.y * r; v.z = t3.x * r; v.w = t3.y * r;
            *reinterpret_cast<float4*>(o + 4) = v;
        }
    }
}

// ---------------- launch ----------------
extern "C" void kernel_launch(void* const* d_in, const int* in_sizes, int n_in,
                              void* d_out, int out_size)
{
    const float* x   = (const float*)d_in[0];
    const float* W1  = (const float*)d_in[1];
    const float* b1  = (const float*)d_in[2];
    const float* W2  = (const float*)d_in[3];
    const float* b2  = (const float*)d_in[4];
    const float* Wc  = (const float*)d_in[5];
    const float* bc  = (const float*)d_in[6];
    const float* We1 = (const float*)d_in[7];
    const float* be1 = (const float*)d_in[8];
    const float* We2 = (const float*)d_in[9];
    const float* be2 = (const float*)d_in[10];
    const float* Wo1 = (const float*)d_in[11];
    const float* bo1 = (const float*)d_in[12];
    const float* Wo2 = (const float*)d_in[13];
    const float* bo2 = (const float*)d_in[14];
    float* out = (float*)d_out;

    float *h1, *df, *ef, *coords, *imp, *pos, *states, *proj, *We2p;
    int* top;
    cudaGetSymbolAddress((void**)&h1,     g_h1);
    cudaGetSymbolAddress((void**)&df,     g_df);
    cudaGetSymbolAddress((void**)&ef,     g_ef);
    cudaGetSymbolAddress((void**)&coords, g_coords);
    cudaGetSymbolAddress((void**)&imp,    g_imp);
    cudaGetSymbolAddress((void**)&top,    g_top);
    cudaGetSymbolAddress((void**)&pos,    g_pos);
    cudaGetSymbolAddress((void**)&states, g_states);
    cudaGetSymbolAddress((void**)&proj,   g_proj);
    cudaGetSymbolAddress((void**)&We2p,   g_We2p);

    // 0) pad We2 -> (512,1152)
    padB_k<<<2304, 256>>>(We2, We2p);
    // 1) h1 = gelu(x @ W1 + b1)
    gemm_k<1,false><<<dim3(4,256), 256>>>(x,  W1, b1, h1, 32768, 512, 512, 512, nullptr, nullptr);
    // 2) df = gelu(h1 @ W2 + b2)
    gemm_k<1,false><<<dim3(4,256), 256>>>(h1, W2, b2, df, 32768, 512, 512, 512, nullptr, nullptr);
    // 3) coords = df @ Wc + bc
    coords_k<<<4096, 256>>>(df, Wc, bc, coords);
    // 4) h1 = gelu(df @ We1[2:,:] + coords @ We1[:2,:] + be1)
    gemm_k<2,false><<<dim3(4,256), 256>>>(df, We1 + 1024, be1, h1, 32768, 512, 512, 512, coords, We1);
    // 5) ef = h1 @ We2 + be2   (padded B)
    gemm_k<0,true><<<dim3(9,256), 256>>>(h1, We2p, be2, ef, 32768, 1027, 512, 1152, nullptr, nullptr);
    // 6) importance
    imp_k<<<4096, 256>>>(ef, imp);
    // 7) top-512 per batch
    topk_k<<<8, 1024>>>(imp, top);
    // 8) gather
    gather_k<<<4096, 256>>>(ef, top, pos, states);
    // 9) h1 = gelu(states @ Wo1 + bo1)   (4096,2048,1024)
    gemm_k<1,false><<<dim3(16,32), 256>>>(states, Wo1, bo1, h1, 4096, 2048, 1024, 2048, nullptr, nullptr);
    // 10) proj = h1 @ Wo2 + bo2          (4096,512,2048) with 64-row tiles
    gemm64_k<<<dim3(4,64), 128>>>(h1, Wo2, bo2, proj, 4096, 512, 2048, 512);
    // 11) fused gaussian attention + einsum
    cudaFuncSetAttribute(attn_k, cudaFuncAttributeMaxDynamicSharedMemorySize, 70656);
    attn_k<<<dim3(313, 8), 256, 69760>>>(pos, proj, out);
}

// round 7
// speedup vs baseline: 1.5271x; 1.5271x over previous
#include <cuda_runtime.h>
#include <math.h>

// ---------------- scratch ----------------
__device__ float g_h1[16777216];      // 32768*512 (reused; also 4096*2048)
__device__ float g_df[16777216];      // 32768*512
__device__ float g_ef[37748736];      // 32768*1152 (padded rows)
__device__ float g_coords[65536];     // 32768*2
__device__ float g_imp[32768];
__device__ int   g_top[4096];         // 8*512
__device__ float g_pos[8192];         // 8*512*2
__device__ float g_states[4194304];   // 4096*1024
__device__ float g_proj[2097152];     // 4096*512
__device__ float g_We2p[589824];      // 512*1152 padded We2
__device__ float g_be2p[1152];        // padded be2

__device__ __forceinline__ float gelu_f(float x) {
    return 0.5f * x * (1.0f + erff(x * 0.70710678118654752440f));
}

// ---- packed fp32x2 helpers (bit-exact fp32, 2x FMA throughput) ----
__device__ __forceinline__ unsigned long long pack2(float x) {
    unsigned long long r;
    asm("mov.b64 %0, {%1, %1};" : "=l"(r) : "f"(x));
    return r;
}
__device__ __forceinline__ void fma2(unsigned long long& d,
                                     unsigned long long a,
                                     unsigned long long b) {
    asm("fma.rn.f32x2 %0, %1, %2, %0;" : "+l"(d) : "l"(a), "l"(b));
}
__device__ __forceinline__ float2 unpack2(unsigned long long p) {
    float2 f;
    asm("mov.b64 {%0, %1}, %2;" : "=f"(f.x), "=f"(f.y) : "l"(p));
    return f;
}

// ---------------- pad We2 (512,1027) -> (512,1152), be2 -> 1152 ----------------
__global__ void __launch_bounds__(256) padB_k(const float* __restrict__ src,
                                              float* __restrict__ dst,
                                              const float* __restrict__ bsrc,
                                              float* __restrict__ bdst)
{
    int i = blockIdx.x * 256 + threadIdx.x;
    if (i < 1152) bdst[i] = (i < 1027) ? bsrc[i] : 0.0f;
    if (i >= 512 * 1152) return;
    int r = i / 1152, c = i - r * 1152;
    dst[i] = (c < 1027) ? src[r * 1027 + c] : 0.0f;
}

// ---------------- tiled fp32 GEMM, 128x128x16, 8x8 per thread, FFMA2 core ----------------
// EPI: 0 = +bias, 1 = gelu(+bias), 2 = gelu(+bias + coords[m,:] @ wtop[:2,n])
template<int EPI>
__global__ void __launch_bounds__(256, 2) gemm_k(
    const float* __restrict__ A, const float* __restrict__ B,
    const float* __restrict__ bias, float* __restrict__ C,
    int M, int N, int K, int ldb,
    const float* __restrict__ coords, const float* __restrict__ wtop)
{
    __shared__ __align__(16) unsigned long long As2[16][130];
    __shared__ __align__(16) float Bs[16][128];

    const int tid = threadIdx.x;
    const int bm  = blockIdx.y * 128;
    const int bn  = blockIdx.x * 128;
    const int tx  = tid & 15;
    const int ty  = tid >> 4;
    const int row = ty * 8;

    unsigned long long acc2[8][4];
    #pragma unroll
    for (int i = 0; i < 8; i++)
        #pragma unroll
        for (int p = 0; p < 4; p++) acc2[i][p] = 0ULL;

    const int rA0 = tid >> 2;
    const int cA4 = tid & 3;
    const int rB0 = tid >> 5;
    const int cB  = (tid & 31) * 4;

    float4 ra0, ra1, rb0, rb1;

    ra0 = *reinterpret_cast<const float4*>(A + (size_t)(bm + rA0) * K + cA4 * 4);
    ra1 = *reinterpret_cast<const float4*>(A + (size_t)(bm + rA0 + 64) * K + cA4 * 4);
    rb0 = *reinterpret_cast<const float4*>(B + (size_t)rB0 * ldb + bn + cB);
    rb1 = *reinterpret_cast<const float4*>(B + (size_t)(rB0 + 8) * ldb + bn + cB);

    for (int k0 = 0; k0 < K; k0 += 16) {
        __syncthreads();
        As2[cA4 * 4 + 0][rA0] = pack2(ra0.x);
        As2[cA4 * 4 + 1][rA0] = pack2(ra0.y);
        As2[cA4 * 4 + 2][rA0] = pack2(ra0.z);
        As2[cA4 * 4 + 3][rA0] = pack2(ra0.w);
        As2[cA4 * 4 + 0][rA0 + 64] = pack2(ra1.x);
        As2[cA4 * 4 + 1][rA0 + 64] = pack2(ra1.y);
        As2[cA4 * 4 + 2][rA0 + 64] = pack2(ra1.z);
        As2[cA4 * 4 + 3][rA0 + 64] = pack2(ra1.w);
        *reinterpret_cast<float4*>(&Bs[rB0][cB])     = rb0;
        *reinterpret_cast<float4*>(&Bs[rB0 + 8][cB]) = rb1;
        __syncthreads();

        if (k0 + 16 < K) {
            int kn = k0 + 16;
            ra0 = *reinterpret_cast<const float4*>(A + (size_t)(bm + rA0) * K + kn + cA4 * 4);
            ra1 = *reinterpret_cast<const float4*>(A + (size_t)(bm + rA0 + 64) * K + kn + cA4 * 4);
            rb0 = *reinterpret_cast<const float4*>(B + (size_t)(kn + rB0) * ldb + bn + cB);
            rb1 = *reinterpret_cast<const float4*>(B + (size_t)(kn + rB0 + 8) * ldb + bn + cB);
        }

        #pragma unroll
        for (int k = 0; k < 16; k++) {
            ulonglong2 A0 = *reinterpret_cast<const ulonglong2*>(&As2[k][row]);
            ulonglong2 A1 = *reinterpret_cast<const ulonglong2*>(&As2[k][row + 2]);
            ulonglong2 A2 = *reinterpret_cast<const ulonglong2*>(&As2[k][row + 4]);
            ulonglong2 A3 = *reinterpret_cast<const ulonglong2*>(&As2[k][row + 6]);
            ulonglong2 B0 = *reinterpret_cast<const ulonglong2*>(&Bs[k][tx * 4]);
            ulonglong2 B1 = *reinterpret_cast<const ulonglong2*>(&Bs[k][64 + tx * 4]);
            fma2(acc2[0][0], A0.x, B0.x); fma2(acc2[0][1], A0.x, B0.y);
            fma2(acc2[0][2], A0.x, B1.x); fma2(acc2[0][3], A0.x, B1.y);
            fma2(acc2[1][0], A0.y, B0.x); fma2(acc2[1][1], A0.y, B0.y);
            fma2(acc2[1][2], A0.y, B1.x); fma2(acc2[1][3], A0.y, B1.y);
            fma2(acc2[2][0], A1.x, B0.x); fma2(acc2[2][1], A1.x, B0.y);
            fma2(acc2[2][2], A1.x, B1.x); fma2(acc2[2][3], A1.x, B1.y);
            fma2(acc2[3][0], A1.y, B0.x); fma2(acc2[3][1], A1.y, B0.y);
            fma2(acc2[3][2], A1.y, B1.x); fma2(acc2[3][3], A1.y, B1.y);
            fma2(acc2[4][0], A2.x, B0.x); fma2(acc2[4][1], A2.x, B0.y);
            fma2(acc2[4][2], A2.x, B1.x); fma2(acc2[4][3], A2.x, B1.y);
            fma2(acc2[5][0], A2.y, B0.x); fma2(acc2[5][1], A2.y, B0.y);
            fma2(acc2[5][2], A2.y, B1.x); fma2(acc2[5][3], A2.y, B1.y);
            fma2(acc2[6][0], A3.x, B0.x); fma2(acc2[6][1], A3.x, B0.y);
            fma2(acc2[6][2], A3.x, B1.x); fma2(acc2[6][3], A3.x, B1.y);
            fma2(acc2[7][0], A3.y, B0.x); fma2(acc2[7][1], A3.y, B0.y);
            fma2(acc2[7][2], A3.y, B1.x); fma2(acc2[7][3], A3.y, B1.y);
        }
    }

    float acc[8][8];
    #pragma unroll
    for (int i = 0; i < 8; i++)
        #pragma unroll
        for (int p = 0; p < 4; p++) {
            float2 t = unpack2(acc2[i][p]);
            acc[i][p * 2 + 0] = t.x;
            acc[i][p * 2 + 1] = t.y;
        }

    float bs[8], w0[8], w1[8];
    #pragma unroll
    for (int h = 0; h < 2; h++)
        #pragma unroll
        for (int jj = 0; jj < 4; jj++) {
            int j = h * 4 + jj;
            int n = bn + h * 64 + tx * 4 + jj;
            bs[j] = bias[n];
            if (EPI == 2) { w0[j] = wtop[n]; w1[j] = wtop[512 + n]; }
        }

    #pragma unroll
    for (int i = 0; i < 8; i++) {
        int gm = bm + row + i;
        float c0 = 0.0f, c1 = 0.0f;
        if (EPI == 2) { c0 = coords[(size_t)gm * 2]; c1 = coords[(size_t)gm * 2 + 1]; }
        #pragma unroll
        for (int h = 0; h < 2; h++) {
            int nb = bn + h * 64 + tx * 4;
            float t[4];
            #pragma unroll
            for (int jj = 0; jj < 4; jj++) {
                int j = h * 4 + jj;
                float val = acc[i][j] + bs[j];
                if (EPI == 2) val += c0 * w0[j] + c1 * w1[j];
                if (EPI >= 1) val = gelu_f(val);
                t[jj] = val;
            }
            float4 v; v.x = t[0]; v.y = t[1]; v.z = t[2]; v.w = t[3];
            *reinterpret_cast<float4*>(C + (size_t)gm * N + nb) = v;
        }
    }
}

// ---------------- coords: (32768,512) @ (512,2) + bc, float4 ----------------
__global__ void __launch_bounds__(256) coords_k(
    const float* __restrict__ df, const float* __restrict__ Wc,
    const float* __restrict__ bc, float* __restrict__ coords)
{
    int r    = blockIdx.x * 8 + (threadIdx.x >> 5);
    int lane = threadIdx.x & 31;
    if (r >= 32768) return;
    const float4* rowp = reinterpret_cast<const float4*>(df + (size_t)r * 512);
    const float4* wc4  = reinterpret_cast<const float4*>(Wc);
    float c0 = 0.0f, c1 = 0.0f;
    #pragma unroll
    for (int it = 0; it < 4; it++) {
        int k4 = it * 32 + lane;
        float4 d = rowp[k4];
        float4 a = wc4[k4 * 2];
        float4 b = wc4[k4 * 2 + 1];
        c0 = fmaf(d.x, a.x, c0); c1 = fmaf(d.x, a.y, c1);
        c0 = fmaf(d.y, a.z, c0); c1 = fmaf(d.y, a.w, c1);
        c0 = fmaf(d.z, b.x, c0); c1 = fmaf(d.z, b.y, c1);
        c0 = fmaf(d.w, b.z, c0); c1 = fmaf(d.w, b.w, c1);
    }
    #pragma unroll
    for (int o = 16; o; o >>= 1) {
        c0 += __shfl_xor_sync(0xffffffffu, c0, o);
        c1 += __shfl_xor_sync(0xffffffffu, c1, o);
    }
    if (lane == 0) {
        coords[(size_t)r * 2]     = c0 + bc[0];
        coords[(size_t)r * 2 + 1] = c1 + bc[1];
    }
}

// ---------------- importance: row L2 norm over first 1027 of 1152-stride rows ----------------
__global__ void __launch_bounds__(256) imp_k(
    const float* __restrict__ ef, float* __restrict__ imp)
{
    int r    = blockIdx.x * 8 + (threadIdx.x >> 5);
    int lane = threadIdx.x & 31;
    if (r >= 32768) return;
    const float* rowp = ef + (size_t)r * 1152;
    float s = 0.0f;
    for (int k = lane; k < 1027; k += 32) {
        float v = rowp[k];
        s = fmaf(v, v, s);
    }
    #pragma unroll
    for (int o = 16; o; o >>= 1) s += __shfl_xor_sync(0xffffffffu, s, o);
    if (lane == 0) imp[r] = sqrtf(s);
}

// ---------------- top-512 of 4096 per batch ----------------
__global__ void __launch_bounds__(1024) topk_k(
    const float* __restrict__ imp, int* __restrict__ top)
{
    __shared__ unsigned long long key[4096];
    int b   = blockIdx.x;
    int tid = threadIdx.x;
    for (int s = tid; s < 4096; s += 1024) {
        unsigned int bits = __float_as_uint(imp[b * 4096 + s]);
        key[s] = ((unsigned long long)(~bits) << 32) | (unsigned int)s;
    }
    for (int k = 2; k <= 4096; k <<= 1) {
        for (int j = k >> 1; j > 0; j >>= 1) {
            __syncthreads();
            for (int idx = tid; idx < 4096; idx += 1024) {
                int l = idx ^ j;
                if (l > idx) {
                    bool asc = ((idx & k) == 0);
                    unsigned long long a = key[idx], c = key[l];
                    if ((a > c) == asc) { key[idx] = c; key[l] = a; }
                }
            }
        }
    }
    __syncthreads();
    if (tid < 512) top[b * 512 + tid] = (int)(key[tid] & 0xffffffffu);
}

// ---------------- gather selected rows (1152-stride source) ----------------
__global__ void __launch_bounds__(256) gather_k(
    const float* __restrict__ ef, const int* __restrict__ top,
    float* __restrict__ pos, float* __restrict__ states)
{
    int rowi = blockIdx.x;
    int b    = rowi >> 9;
    int s    = top[rowi];
    const float* src = ef + (size_t)(b * 4096 + s) * 1152;
    if (threadIdx.x < 2) pos[rowi * 2 + threadIdx.x] = src[threadIdx.x];
    for (int d = threadIdx.x; d < 1024; d += 256)
        states[(size_t)rowi * 1024 + d] = src[2 + d];
}

// ---------------- fused gaussian attention + einsum (R5-proven layout) ----------------
__global__ void __launch_bounds__(256, 2) attn_k(
    const float* __restrict__ pos, const float* __restrict__ proj,
    float* __restrict__ out)
{
    extern __shared__ float sm[];
    float* spx  = sm;                  // 512
    float* spy  = spx + 512;           // 512
    float* sa   = spy + 512;           // 32*512
    float* rinv = sa + 32 * 512;       // 32

    const int b   = blockIdx.y;
    const int g0  = blockIdx.x * 32;
    const int tid = threadIdx.x;

    for (int n = tid; n < 512; n += 256) {
        spx[n] = pos[(b * 512 + n) * 2];
        spy[n] = pos[(b * 512 + n) * 2 + 1];
    }
    __syncthreads();

    for (int e = tid; e < 32 * 512; e += 256) {
        int i  = e >> 9;
        int n  = e & 511;
        int gi = g0 + i;
        float a = 0.0f;
        if (gi < 10000) {
            int ix = gi / 100, iy = gi - ix * 100;
            float gx = (ix == 99) ? 1.0f : -1.0f + (float)ix * (2.0f / 99.0f);
            float gy = (iy == 99) ? 1.0f : -1.0f + (float)iy * (2.0f / 99.0f);
            float dx = gx - spx[n];
            float dy = gy - spy[n];
            float sq = fmaf(dx, dx, dy * dy);
            a = __expf(sq * -10.0f);
        }
        sa[i * 512 + n] = a;
    }
    __syncthreads();

    int warp = tid >> 5, lane = tid & 31;
    for (int i = warp; i < 32; i += 8) {
        float s = 0.0f;
        for (int n = lane; n < 512; n += 32) s += sa[i * 512 + n];
        #pragma unroll
        for (int o = 16; o; o >>= 1) s += __shfl_xor_sync(0xffffffffu, s, o);
        if (lane == 0) rinv[i] = 1.0f / (s + 1e-8f);
    }
    __syncthreads();

    const int ig = tid >> 5;           // rows ig*4..+3
    const int dg = tid & 31;           // cols dg*4 + q*128
    const float* pb = proj + (size_t)b * 512 * 512;
    unsigned long long acc[4][8];
    #pragma unroll
    for (int i = 0; i < 4; i++)
        #pragma unroll
        for (int j = 0; j < 8; j++) acc[i][j] = 0ULL;

    #pragma unroll 2
    for (int n = 0; n < 512; n++) {
        unsigned long long pa0 = pack2(sa[(ig * 4 + 0) * 512 + n]);
        unsigned long long pa1 = pack2(sa[(ig * 4 + 1) * 512 + n]);
        unsigned long long pa2 = pack2(sa[(ig * 4 + 2) * 512 + n]);
        unsigned long long pa3 = pack2(sa[(ig * 4 + 3) * 512 + n]);
        const float* prow = pb + (size_t)n * 512 + dg * 4;
        #pragma unroll
        for (int q = 0; q < 4; q++) {
            ulonglong2 v = *reinterpret_cast<const ulonglong2*>(prow + q * 128);
            fma2(acc[0][q * 2],     pa0, v.x);
            fma2(acc[0][q * 2 + 1], pa0, v.y);
            fma2(acc[1][q * 2],     pa1, v.x);
            fma2(acc[1][q * 2 + 1], pa1, v.y);
            fma2(acc[2][q * 2],     pa2, v.x);
            fma2(acc[2][q * 2 + 1], pa2, v.y);
            fma2(acc[3][q * 2],     pa3, v.x);
            fma2(acc[3][q * 2 + 1], pa3, v.y);
        }
    }

    #pragma unroll
    for (int ii = 0; ii < 4; ii++) {
        int gi = g0 + ig * 4 + ii;
        if (gi < 10000) {
            float r = rinv[ig * 4 + ii];
            float* o = out + ((size_t)b * 10000 + gi) * 512 + dg * 4;
            #pragma unroll
            for (int q = 0; q < 4; q++) {
                float2 t0 = unpack2(acc[ii][q * 2]);
                float2 t1 = unpack2(acc[ii][q * 2 + 1]);
                float4 v;
                v.x = t0.x * r;
                v.y = t0.y * r;
                v.z = t1.x * r;
                v.w = t1.y * r;
                *reinterpret_cast<float4*>(o + q * 128) = v;
            }
        }
    }
}

// ---------------- launch ----------------
extern "C" void kernel_launch(void* const* d_in, const int* in_sizes, int n_in,
                              void* d_out, int out_size)
{
    const float* x   = (const float*)d_in[0];
    const float* W1  = (const float*)d_in[1];
    const float* b1  = (const float*)d_in[2];
    const float* W2  = (const float*)d_in[3];
    const float* b2  = (const float*)d_in[4];
    const float* Wc  = (const float*)d_in[5];
    const float* bc  = (const float*)d_in[6];
    const float* We1 = (const float*)d_in[7];
    const float* be1 = (const float*)d_in[8];
    const float* We2 = (const float*)d_in[9];
    const float* be2 = (const float*)d_in[10];
    const float* Wo1 = (const float*)d_in[11];
    const float* bo1 = (const float*)d_in[12];
    const float* Wo2 = (const float*)d_in[13];
    const float* bo2 = (const float*)d_in[14];
    float* out = (float*)d_out;

    float *h1, *df, *ef, *coords, *imp, *pos, *states, *proj, *We2p, *be2p;
    int* top;
    cudaGetSymbolAddress((void**)&h1,     g_h1);
    cudaGetSymbolAddress((void**)&df,     g_df);
    cudaGetSymbolAddress((void**)&ef,     g_ef);
    cudaGetSymbolAddress((void**)&coords, g_coords);
    cudaGetSymbolAddress((void**)&imp,    g_imp);
    cudaGetSymbolAddress((void**)&top,    g_top);
    cudaGetSymbolAddress((void**)&pos,    g_pos);
    cudaGetSymbolAddress((void**)&states, g_states);
    cudaGetSymbolAddress((void**)&proj,   g_proj);
    cudaGetSymbolAddress((void**)&We2p,   g_We2p);
    cudaGetSymbolAddress((void**)&be2p,   g_be2p);

    // 0) pad We2 -> (512,1152), be2 -> 1152
    padB_k<<<2304, 256>>>(We2, We2p, be2, be2p);
    // 1) h1 = gelu(x @ W1 + b1)
    gemm_k<1><<<dim3(4,256), 256>>>(x,  W1, b1, h1, 32768, 512, 512, 512, nullptr, nullptr);
    // 2) df = gelu(h1 @ W2 + b2)
    gemm_k<1><<<dim3(4,256), 256>>>(h1, W2, b2, df, 32768, 512, 512, 512, nullptr, nullptr);
    // 3) coords = df @ Wc + bc
    coords_k<<<4096, 256>>>(df, Wc, bc, coords);
    // 4) h1 = gelu(df @ We1[2:,:] + coords @ We1[:2,:] + be1)
    gemm_k<2><<<dim3(4,256), 256>>>(df, We1 + 1024, be1, h1, 32768, 512, 512, 512, coords, We1);
    // 5) ef = h1 @ We2p + be2p   (N=1152 padded, fully vectorized)
    gemm_k<0><<<dim3(9,256), 256>>>(h1, We2p, be2p, ef, 32768, 1152, 512, 1152, nullptr, nullptr);
    // 6) importance
    imp_k<<<4096, 256>>>(ef, imp);
    // 7) top-512 per batch
    topk_k<<<8, 1024>>>(imp, top);
    // 8) gather
    gather_k<<<4096, 256>>>(ef, top, pos, states);
    // 9) h1 = gelu(states @ Wo1 + bo1)   (4096,2048,1024)
    gemm_k<1><<<dim3(16,32), 256>>>(states, Wo1, bo1, h1, 4096, 2048, 1024, 2048, nullptr, nullptr);
    // 10) proj = h1 @ Wo2 + bo2          (4096,512,2048)
    gemm_k<0><<<dim3(4,32), 256>>>(h1, Wo2, bo2, proj, 4096, 512, 2048, 512, nullptr, nullptr);
    // 11) fused gaussian attention + einsum
    cudaFuncSetAttribute(attn_k, cudaFuncAttributeMaxDynamicSharedMemorySize, 70656);
    attn_k<<<dim3(313, 8), 256, 69760>>>(pos, proj, out);
}

// round 8
// speedup vs baseline: 1.5598x; 1.0214x over previous
#include <cuda_runtime.h>
#include <math.h>

// ---------------- scratch ----------------
__device__ float g_h1[16777216];      // 32768*512 (reused; also 4096*2048)
__device__ float g_df[16777216];      // 32768*512
__device__ float g_ef[37748736];      // 32768*1152 (padded rows)
__device__ float g_coords[65536];     // 32768*2
__device__ float g_imp[32768];
__device__ int   g_top[4096];         // 8*512
__device__ float g_pos[8192];         // 8*512*2
__device__ float g_states[4194304];   // 4096*1024
__device__ float g_proj[2097152];     // 4096*512
__device__ float g_We2p[589824];      // 512*1152 padded We2
__device__ float g_be2p[1152];        // padded be2

__device__ __forceinline__ float gelu_f(float x) {
    return 0.5f * x * (1.0f + erff(x * 0.70710678118654752440f));
}

// ---- packed fp32x2 helpers (bit-exact fp32, 2x FMA throughput) ----
__device__ __forceinline__ unsigned long long pack2(float x) {
    unsigned long long r;
    asm("mov.b64 %0, {%1, %1};" : "=l"(r) : "f"(x));
    return r;
}
__device__ __forceinline__ void fma2(unsigned long long& d,
                                     unsigned long long a,
                                     unsigned long long b) {
    asm("fma.rn.f32x2 %0, %1, %2, %0;" : "+l"(d) : "l"(a), "l"(b));
}
__device__ __forceinline__ float2 unpack2(unsigned long long p) {
    float2 f;
    asm("mov.b64 {%0, %1}, %2;" : "=f"(f.x), "=f"(f.y) : "l"(p));
    return f;
}

// ---------------- pad We2 (512,1027) -> (512,1152), be2 -> 1152 ----------------
__global__ void __launch_bounds__(256) padB_k(const float* __restrict__ src,
                                              float* __restrict__ dst,
                                              const float* __restrict__ bsrc,
                                              float* __restrict__ bdst)
{
    int i = blockIdx.x * 256 + threadIdx.x;
    if (i < 1152) bdst[i] = (i < 1027) ? bsrc[i] : 0.0f;
    if (i >= 512 * 1152) return;
    int r = i / 1152, c = i - r * 1152;
    dst[i] = (c < 1027) ? src[r * 1027 + c] : 0.0f;
}

// ---------------- tiled fp32 GEMM, 128x128x16, 8x8/thread, FFMA2, double-buffered ----------------
// EPI: 0 = +bias, 1 = gelu(+bias), 2 = gelu(+bias + coords[m,:] @ wtop[:2,n])
template<int EPI>
__global__ void __launch_bounds__(256, 2) gemm_k(
    const float* __restrict__ A, const float* __restrict__ B,
    const float* __restrict__ bias, float* __restrict__ C,
    int M, int N, int K, int ldb,
    const float* __restrict__ coords, const float* __restrict__ wtop)
{
    __shared__ __align__(16) unsigned long long As2[2][16][130];
    __shared__ __align__(16) float Bs[2][16][128];

    const int tid = threadIdx.x;
    const int bm  = blockIdx.y * 128;
    const int bn  = blockIdx.x * 128;
    const int tx  = tid & 15;
    const int ty  = tid >> 4;
    const int row = ty * 8;

    unsigned long long acc2[8][4];
    #pragma unroll
    for (int i = 0; i < 8; i++)
        #pragma unroll
        for (int p = 0; p < 4; p++) acc2[i][p] = 0ULL;

    const int rA0 = tid >> 2;
    const int cA4 = tid & 3;
    const int rB0 = tid >> 5;
    const int cB  = (tid & 31) * 4;

    float4 ra0, ra1, rb0, rb1;

    // prefetch tile 0 and store to buffer 0
    ra0 = *reinterpret_cast<const float4*>(A + (size_t)(bm + rA0) * K + cA4 * 4);
    ra1 = *reinterpret_cast<const float4*>(A + (size_t)(bm + rA0 + 64) * K + cA4 * 4);
    rb0 = *reinterpret_cast<const float4*>(B + (size_t)rB0 * ldb + bn + cB);
    rb1 = *reinterpret_cast<const float4*>(B + (size_t)(rB0 + 8) * ldb + bn + cB);
    As2[0][cA4 * 4 + 0][rA0] = pack2(ra0.x);
    As2[0][cA4 * 4 + 1][rA0] = pack2(ra0.y);
    As2[0][cA4 * 4 + 2][rA0] = pack2(ra0.z);
    As2[0][cA4 * 4 + 3][rA0] = pack2(ra0.w);
    As2[0][cA4 * 4 + 0][rA0 + 64] = pack2(ra1.x);
    As2[0][cA4 * 4 + 1][rA0 + 64] = pack2(ra1.y);
    As2[0][cA4 * 4 + 2][rA0 + 64] = pack2(ra1.z);
    As2[0][cA4 * 4 + 3][rA0 + 64] = pack2(ra1.w);
    *reinterpret_cast<float4*>(&Bs[0][rB0][cB])     = rb0;
    *reinterpret_cast<float4*>(&Bs[0][rB0 + 8][cB]) = rb1;
    __syncthreads();

    const int T = K >> 4;
    for (int t = 0; t < T; t++) {
        const int cur = t & 1;
        // prefetch next tile into registers (overlaps compute below)
        if (t + 1 < T) {
            int kn = (t + 1) << 4;
            ra0 = *reinterpret_cast<const float4*>(A + (size_t)(bm + rA0) * K + kn + cA4 * 4);
            ra1 = *reinterpret_cast<const float4*>(A + (size_t)(bm + rA0 + 64) * K + kn + cA4 * 4);
            rb0 = *reinterpret_cast<const float4*>(B + (size_t)(kn + rB0) * ldb + bn + cB);
            rb1 = *reinterpret_cast<const float4*>(B + (size_t)(kn + rB0 + 8) * ldb + bn + cB);
        }

        // compute current tile
        #pragma unroll
        for (int k = 0; k < 16; k++) {
            ulonglong2 A0 = *reinterpret_cast<const ulonglong2*>(&As2[cur][k][row]);
            ulonglong2 A1 = *reinterpret_cast<const ulonglong2*>(&As2[cur][k][row + 2]);
            ulonglong2 A2 = *reinterpret_cast<const ulonglong2*>(&As2[cur][k][row + 4]);
            ulonglong2 A3 = *reinterpret_cast<const ulonglong2*>(&As2[cur][k][row + 6]);
            ulonglong2 B0 = *reinterpret_cast<const ulonglong2*>(&Bs[cur][k][tx * 4]);
            ulonglong2 B1 = *reinterpret_cast<const ulonglong2*>(&Bs[cur][k][64 + tx * 4]);
            fma2(acc2[0][0], A0.x, B0.x); fma2(acc2[0][1], A0.x, B0.y);
            fma2(acc2[0][2], A0.x, B1.x); fma2(acc2[0][3], A0.x, B1.y);
            fma2(acc2[1][0], A0.y, B0.x); fma2(acc2[1][1], A0.y, B0.y);
            fma2(acc2[1][2], A0.y, B1.x); fma2(acc2[1][3], A0.y, B1.y);
            fma2(acc2[2][0], A1.x, B0.x); fma2(acc2[2][1], A1.x, B0.y);
            fma2(acc2[2][2], A1.x, B1.x); fma2(acc2[2][3], A1.x, B1.y);
            fma2(acc2[3][0], A1.y, B0.x); fma2(acc2[3][1], A1.y, B0.y);
            fma2(acc2[3][2], A1.y, B1.x); fma2(acc2[3][3], A1.y, B1.y);
            fma2(acc2[4][0], A2.x, B0.x); fma2(acc2[4][1], A2.x, B0.y);
            fma2(acc2[4][2], A2.x, B1.x); fma2(acc2[4][3], A2.x, B1.y);
            fma2(acc2[5][0], A2.y, B0.x); fma2(acc2[5][1], A2.y, B0.y);
            fma2(acc2[5][2], A2.y, B1.x); fma2(acc2[5][3], A2.y, B1.y);
            fma2(acc2[6][0], A3.x, B0.x); fma2(acc2[6][1], A3.x, B0.y);
            fma2(acc2[6][2], A3.x, B1.x); fma2(acc2[6][3], A3.x, B1.y);
            fma2(acc2[7][0], A3.y, B0.x); fma2(acc2[7][1], A3.y, B0.y);
            fma2(acc2[7][2], A3.y, B1.x); fma2(acc2[7][3], A3.y, B1.y);
        }

        // store next tile into the other buffer; single barrier per tile
        if (t + 1 < T) {
            const int nxt = cur ^ 1;
            As2[nxt][cA4 * 4 + 0][rA0] = pack2(ra0.x);
            As2[nxt][cA4 * 4 + 1][rA0] = pack2(ra0.y);
            As2[nxt][cA4 * 4 + 2][rA0] = pack2(ra0.z);
            As2[nxt][cA4 * 4 + 3][rA0] = pack2(ra0.w);
            As2[nxt][cA4 * 4 + 0][rA0 + 64] = pack2(ra1.x);
            As2[nxt][cA4 * 4 + 1][rA0 + 64] = pack2(ra1.y);
            As2[nxt][cA4 * 4 + 2][rA0 + 64] = pack2(ra1.z);
            As2[nxt][cA4 * 4 + 3][rA0 + 64] = pack2(ra1.w);
            *reinterpret_cast<float4*>(&Bs[nxt][rB0][cB])     = rb0;
            *reinterpret_cast<float4*>(&Bs[nxt][rB0 + 8][cB]) = rb1;
            __syncthreads();
        }
    }

    float acc[8][8];
    #pragma unroll
    for (int i = 0; i < 8; i++)
        #pragma unroll
        for (int p = 0; p < 4; p++) {
            float2 t = unpack2(acc2[i][p]);
            acc[i][p * 2 + 0] = t.x;
            acc[i][p * 2 + 1] = t.y;
        }

    float bs[8], w0[8], w1[8];
    #pragma unroll
    for (int h = 0; h < 2; h++)
        #pragma unroll
        for (int jj = 0; jj < 4; jj++) {
            int j = h * 4 + jj;
            int n = bn + h * 64 + tx * 4 + jj;
            bs[j] = bias[n];
            if (EPI == 2) { w0[j] = wtop[n]; w1[j] = wtop[512 + n]; }
        }

    #pragma unroll
    for (int i = 0; i < 8; i++) {
        int gm = bm + row + i;
        float c0 = 0.0f, c1 = 0.0f;
        if (EPI == 2) { c0 = coords[(size_t)gm * 2]; c1 = coords[(size_t)gm * 2 + 1]; }
        #pragma unroll
        for (int h = 0; h < 2; h++) {
            int nb = bn + h * 64 + tx * 4;
            float t[4];
            #pragma unroll
            for (int jj = 0; jj < 4; jj++) {
                int j = h * 4 + jj;
                float val = acc[i][j] + bs[j];
                if (EPI == 2) val += c0 * w0[j] + c1 * w1[j];
                if (EPI >= 1) val = gelu_f(val);
                t[jj] = val;
            }
            float4 v; v.x = t[0]; v.y = t[1]; v.z = t[2]; v.w = t[3];
            *reinterpret_cast<float4*>(C + (size_t)gm * N + nb) = v;
        }
    }
}

// ---------------- coords: (32768,512) @ (512,2) + bc, float4 ----------------
__global__ void __launch_bounds__(256) coords_k(
    const float* __restrict__ df, const float* __restrict__ Wc,
    const float* __restrict__ bc, float* __restrict__ coords)
{
    int r    = blockIdx.x * 8 + (threadIdx.x >> 5);
    int lane = threadIdx.x & 31;
    if (r >= 32768) return;
    const float4* rowp = reinterpret_cast<const float4*>(df + (size_t)r * 512);
    const float4* wc4  = reinterpret_cast<const float4*>(Wc);
    float c0 = 0.0f, c1 = 0.0f;
    #pragma unroll
    for (int it = 0; it < 4; it++) {
        int k4 = it * 32 + lane;
        float4 d = rowp[k4];
        float4 a = wc4[k4 * 2];
        float4 b = wc4[k4 * 2 + 1];
        c0 = fmaf(d.x, a.x, c0); c1 = fmaf(d.x, a.y, c1);
        c0 = fmaf(d.y, a.z, c0); c1 = fmaf(d.y, a.w, c1);
        c0 = fmaf(d.z, b.x, c0); c1 = fmaf(d.z, b.y, c1);
        c0 = fmaf(d.w, b.z, c0); c1 = fmaf(d.w, b.w, c1);
    }
    #pragma unroll
    for (int o = 16; o; o >>= 1) {
        c0 += __shfl_xor_sync(0xffffffffu, c0, o);
        c1 += __shfl_xor_sync(0xffffffffu, c1, o);
    }
    if (lane == 0) {
        coords[(size_t)r * 2]     = c0 + bc[0];
        coords[(size_t)r * 2 + 1] = c1 + bc[1];
    }
}

// ---------------- importance: row L2 norm (1027 of 1152-stride), float4 ----------------
__global__ void __launch_bounds__(256) imp_k(
    const float* __restrict__ ef, float* __restrict__ imp)
{
    int r    = blockIdx.x * 8 + (threadIdx.x >> 5);
    int lane = threadIdx.x & 31;
    if (r >= 32768) return;
    const float4* rowp = reinterpret_cast<const float4*>(ef + (size_t)r * 1152);
    float s = 0.0f;
    #pragma unroll
    for (int it = 0; it < 8; it++) {
        float4 v = rowp[it * 32 + lane];
        s = fmaf(v.x, v.x, s);
        s = fmaf(v.y, v.y, s);
        s = fmaf(v.z, v.z, s);
        s = fmaf(v.w, v.w, s);
    }
    if (lane < 3) {
        float v = ef[(size_t)r * 1152 + 1024 + lane];
        s = fmaf(v, v, s);
    }
    #pragma unroll
    for (int o = 16; o; o >>= 1) s += __shfl_xor_sync(0xffffffffu, s, o);
    if (lane == 0) imp[r] = sqrtf(s);
}

// ---------------- top-512 of 4096 per batch ----------------
__global__ void __launch_bounds__(1024) topk_k(
    const float* __restrict__ imp, int* __restrict__ top)
{
    __shared__ unsigned long long key[4096];
    int b   = blockIdx.x;
    int tid = threadIdx.x;
    for (int s = tid; s < 4096; s += 1024) {
        unsigned int bits = __float_as_uint(imp[b * 4096 + s]);
        key[s] = ((unsigned long long)(~bits) << 32) | (unsigned int)s;
    }
    for (int k = 2; k <= 4096; k <<= 1) {
        for (int j = k >> 1; j > 0; j >>= 1) {
            __syncthreads();
            for (int idx = tid; idx < 4096; idx += 1024) {
                int l = idx ^ j;
                if (l > idx) {
                    bool asc = ((idx & k) == 0);
                    unsigned long long a = key[idx], c = key[l];
                    if ((a > c) == asc) { key[idx] = c; key[l] = a; }
                }
            }
        }
    }
    __syncthreads();
    if (tid < 512) top[b * 512 + tid] = (int)(key[tid] & 0xffffffffu);
}

// ---------------- gather selected rows (1152-stride source) ----------------
__global__ void __launch_bounds__(256) gather_k(
    const float* __restrict__ ef, const int* __restrict__ top,
    float* __restrict__ pos, float* __restrict__ states)
{
    int rowi = blockIdx.x;
    int b    = rowi >> 9;
    int s    = top[rowi];
    const float* src = ef + (size_t)(b * 4096 + s) * 1152;
    if (threadIdx.x < 2) pos[rowi * 2 + threadIdx.x] = src[threadIdx.x];
    for (int d = threadIdx.x; d < 1024; d += 256)
        states[(size_t)rowi * 1024 + d] = src[2 + d];
}

// ---------------- fused gaussian attention + einsum ----------------
// 32 grid points x 512 entities per block; thread: 8 g-rows x 8 d-cols
__global__ void __launch_bounds__(256, 2) attn_k(
    const float* __restrict__ pos, const float* __restrict__ proj,
    float* __restrict__ out)
{
    extern __shared__ float sm[];
    float* spx  = sm;                  // 512
    float* spy  = spx + 512;           // 512
    float* sa   = spy + 512;           // 32*512
    float* rinv = sa + 32 * 512;       // 32

    const int b   = blockIdx.y;
    const int g0  = blockIdx.x * 32;
    const int tid = threadIdx.x;

    for (int n = tid; n < 512; n += 256) {
        spx[n] = pos[(b * 512 + n) * 2];
        spy[n] = pos[(b * 512 + n) * 2 + 1];
    }
    __syncthreads();

    for (int e = tid; e < 32 * 512; e += 256) {
        int i  = e >> 9;
        int n  = e & 511;
        int gi = g0 + i;
        float a = 0.0f;
        if (gi < 10000) {
            int ix = gi / 100, iy = gi - ix * 100;
            float gx = (ix == 99) ? 1.0f : -1.0f + (float)ix * (2.0f / 99.0f);
            float gy = (iy == 99) ? 1.0f : -1.0f + (float)iy * (2.0f / 99.0f);
            float dx = gx - spx[n];
            float dy = gy - spy[n];
            float sq = fmaf(dx, dx, dy * dy);
            a = __expf(sq * -10.0f);
        }
        sa[i * 512 + n] = a;
    }
    __syncthreads();

    int warp = tid >> 5, lane = tid & 31;
    for (int i = warp; i < 32; i += 8) {
        float s = 0.0f;
        for (int n = lane; n < 512; n += 32) s += sa[i * 512 + n];
        #pragma unroll
        for (int o = 16; o; o >>= 1) s += __shfl_xor_sync(0xffffffffu, s, o);
        if (lane == 0) rinv[i] = 1.0f / (s + 1e-8f);
    }
    __syncthreads();

    // 32x512 = sa(32x512) @ proj_b(512x512); thread: 8 g-rows x 8 d-cols
    const int gg = tid >> 6;           // 0..3 -> rows gg*8..+7
    const int dt = tid & 63;           // cols dt*8..+7
    const float* pb   = proj + (size_t)b * 512 * 512 + dt * 8;
    const float* saro = sa + gg * 8 * 512;
    unsigned long long acc[8][4];
    #pragma unroll
    for (int i = 0; i < 8; i++)
        #pragma unroll
        for (int p = 0; p < 4; p++) acc[i][p] = 0ULL;

    for (int n = 0; n < 512; n++) {
        ulonglong2 v0 = *reinterpret_cast<const ulonglong2*>(pb + (size_t)n * 512);
        ulonglong2 v1 = *reinterpret_cast<const ulonglong2*>(pb + (size_t)n * 512 + 4);
        #pragma unroll
        for (int i = 0; i < 8; i++) {
            unsigned long long pa = pack2(saro[i * 512 + n]);
            fma2(acc[i][0], pa, v0.x);
            fma2(acc[i][1], pa, v0.y);
            fma2(acc[i][2], pa, v1.x);
            fma2(acc[i][3], pa, v1.y);
        }
    }

    #pragma unroll
    for (int i = 0; i < 8; i++) {
        int gi = g0 + gg * 8 + i;
        if (gi < 10000) {
            float r = rinv[gg * 8 + i];
            float* o = out + ((size_t)b * 10000 + gi) * 512 + dt * 8;
            float2 t0 = unpack2(acc[i][0]);
            float2 t1 = unpack2(acc[i][1]);
            float2 t2 = unpack2(acc[i][2]);
            float2 t3 = unpack2(acc[i][3]);
            float4 v;
            v.x = t0.x * r; v.y = t0.y * r; v.z = t1.x * r; v.w = t1.y * r;
            *reinterpret_cast<float4*>(o) = v;
            v.x = t2.x * r; v.y = t2.y * r; v.z = t3.x * r; v.w = t3.y * r;
            *reinterpret_cast<float4*>(o + 4) = v;
        }
    }
}

// ---------------- launch ----------------
extern "C" void kernel_launch(void* const* d_in, const int* in_sizes, int n_in,
                              void* d_out, int out_size)
{
    const float* x   = (const float*)d_in[0];
    const float* W1  = (const float*)d_in[1];
    const float* b1  = (const float*)d_in[2];
    const float* W2  = (const float*)d_in[3];
    const float* b2  = (const float*)d_in[4];
    const float* Wc  = (const float*)d_in[5];
    const float* bc  = (const float*)d_in[6];
    const float* We1 = (const float*)d_in[7];
    const float* be1 = (const float*)d_in[8];
    const float* We2 = (const float*)d_in[9];
    const float* be2 = (const float*)d_in[10];
    const float* Wo1 = (const float*)d_in[11];
    const float* bo1 = (const float*)d_in[12];
    const float* Wo2 = (const float*)d_in[13];
    const float* bo2 = (const float*)d_in[14];
    float* out = (float*)d_out;

    float *h1, *df, *ef, *coords, *imp, *pos, *states, *proj, *We2p, *be2p;
    int* top;
    cudaGetSymbolAddress((void**)&h1,     g_h1);
    cudaGetSymbolAddress((void**)&df,     g_df);
    cudaGetSymbolAddress((void**)&ef,     g_ef);
    cudaGetSymbolAddress((void**)&coords, g_coords);
    cudaGetSymbolAddress((void**)&imp,    g_imp);
    cudaGetSymbolAddress((void**)&top,    g_top);
    cudaGetSymbolAddress((void**)&pos,    g_pos);
    cudaGetSymbolAddress((void**)&states, g_states);
    cudaGetSymbolAddress((void**)&proj,   g_proj);
    cudaGetSymbolAddress((void**)&We2p,   g_We2p);
    cudaGetSymbolAddress((void**)&be2p,   g_be2p);

    // 0) pad We2 -> (512,1152), be2 -> 1152
    padB_k<<<2304, 256>>>(We2, We2p, be2, be2p);
    // 1) h1 = gelu(x @ W1 + b1)
    gemm_k<1><<<dim3(4,256), 256>>>(x,  W1, b1, h1, 32768, 512, 512, 512, nullptr, nullptr);
    // 2) df = gelu(h1 @ W2 + b2)
    gemm_k<1><<<dim3(4,256), 256>>>(h1, W2, b2, df, 32768, 512, 512, 512, nullptr, nullptr);
    // 3) coords = df @ Wc + bc
    coords_k<<<4096, 256>>>(df, Wc, bc, coords);
    // 4) h1 = gelu(df @ We1[2:,:] + coords @ We1[:2,:] + be1)
    gemm_k<2><<<dim3(4,256), 256>>>(df, We1 + 1024, be1, h1, 32768, 512, 512, 512, coords, We1);
    // 5) ef = h1 @ We2p + be2p   (N=1152 padded, fully vectorized)
    gemm_k<0><<<dim3(9,256), 256>>>(h1, We2p, be2p, ef, 32768, 1152, 512, 1152, nullptr, nullptr);
    // 6) importance
    imp_k<<<4096, 256>>>(ef, imp);
    // 7) top-512 per batch
    topk_k<<<8, 1024>>>(imp, top);
    // 8) gather
    gather_k<<<4096, 256>>>(ef, top, pos, states);
    // 9) h1 = gelu(states @ Wo1 + bo1)   (4096,2048,1024)
    gemm_k<1><<<dim3(16,32), 256>>>(states, Wo1, bo1, h1, 4096, 2048, 1024, 2048, nullptr, nullptr);
    // 10) proj = h1 @ Wo2 + bo2          (4096,512,2048)
    gemm_k<0><<<dim3(4,32), 256>>>(h1, Wo2, bo2, proj, 4096, 512, 2048, 512, nullptr, nullptr);
    // 11) fused gaussian attention + einsum
    cudaFuncSetAttribute(attn_k, cudaFuncAttributeMaxDynamicSharedMemorySize, 70656);
    attn_k<<<dim3(313, 8), 256, 69760>>>(pos, proj, out);
}